// round 12
// baseline (speedup 1.0000x reference)
#include <cuda_runtime.h>
#include <math.h>
#include <stdint.h>

#define MAX_N  1024
#define MAX_P  32768           // directed edges upper bound
#define EPS    1e-4f
#define ZCHUNK 32768           // bytes per bulk store
#define ZPER   4               // chunks per CTA

// ---- scratch (__device__ globals; no allocation allowed) ----
__device__ float g_diag [MAX_N * 64];          // per-node sum of R^T R
__device__ float g_dis  [MAX_N * 64];          // per-node D^{-1/2}
__device__ float g_norm [MAX_P * 64];          // N_p = R_p @ Dis[head(p)]
__device__ float g_stage[(MAX_P + MAX_N) * 64]; // staged nonzero 8x8 blocks

// ---- zero one byte-range of the output via TMA bulk stores ----
__global__ void k_zero_tma(char* __restrict__ out, size_t total) {
    __shared__ __align__(128) char buf[ZCHUNK];
    float4* b4 = (float4*)buf;
    for (int t = threadIdx.x; t < ZCHUNK / 16; t += blockDim.x)
        b4[t] = make_float4(0.f, 0.f, 0.f, 0.f);
    __syncthreads();
    asm volatile("fence.proxy.async.shared::cta;" ::: "memory");
    if (threadIdx.x == 0) {
        uint32_t saddr;
        asm("{ .reg .u64 t; cvta.to.shared.u64 t, %1; cvt.u32.u64 %0, t; }"
            : "=r"(saddr) : "l"(buf));
        size_t base = (size_t)blockIdx.x * (ZPER * (size_t)ZCHUNK);
#pragma unroll
        for (int k = 0; k < ZPER; k++) {
            size_t off = base + (size_t)k * ZCHUNK;
            if (off >= total) break;
            size_t rem = total - off;
            unsigned len = (unsigned)(rem >= ZCHUNK ? ZCHUNK : rem);
            asm volatile(
                "cp.async.bulk.global.shared::cta.bulk_group [%0], [%1], %2;"
                :: "l"(out + off), "r"(saddr), "r"(len) : "memory");
        }
        asm volatile("cp.async.bulk.commit_group;" ::: "memory");
        asm volatile("cp.async.bulk.wait_group 0;" ::: "memory");
    }
}

// ---- k_ftf v2: smem-staged R^T R, atomically accumulated into g_diag[i] ----
__global__ void k_ftf(const float* __restrict__ R, const int* __restrict__ E, int P) {
    __shared__ float Rs[4][64];
    int sub = threadIdx.x >> 6;
    int t   = threadIdx.x & 63;
    int p   = blockIdx.x * 4 + sub;
    bool valid = (p < P);
    if (valid && t < 16)
        ((float4*)Rs[sub])[t] = ((const float4*)(R + (size_t)p * 64))[t];
    __syncthreads();
    if (!valid) return;
    int r = t >> 3, c = t & 7;
    float v = 0.f;
#pragma unroll
    for (int k = 0; k < 8; k++) v += Rs[sub][k * 8 + r] * Rs[sub][k * 8 + c];
    int i = E[2 * p];
    atomicAdd(&g_diag[i * 64 + t], v);
}

// ---- per-node D^{-1/2} via coupled Newton-Schulz; 4 nodes per 256-thread CTA ----
__global__ void k_ns(int n) {
    __shared__ float Y[4][64], Z[4][64], G[4][64], red[4][64];
    int sub = threadIdx.x >> 6;
    int t   = threadIdx.x & 63;
    int v   = blockIdx.x * 4 + sub;
    int vc  = (v < n) ? v : (n - 1);
    int r = t >> 3, c = t & 7;

    float a = g_diag[vc * 64 + r * 8 + c];
    float b = g_diag[vc * 64 + c * 8 + r];
    float d = 0.5f * (a + b) + ((r == c) ? EPS : 0.f);

    red[sub][t] = d * d;
    __syncthreads();
    if (t < 32) red[sub][t] += red[sub][t + 32];
    __syncthreads();
    if (t < 16) red[sub][t] += red[sub][t + 16];
    __syncthreads();
    if (t < 8)  red[sub][t] += red[sub][t + 8];
    __syncthreads();
    if (t < 4)  red[sub][t] += red[sub][t + 4];
    __syncthreads();
    if (t < 2)  red[sub][t] += red[sub][t + 2];
    __syncthreads();
    if (t == 0) red[sub][0] += red[sub][1];
    __syncthreads();
    float s = sqrtf(red[sub][0]);
    float inv_s = 1.f / s;

    Y[sub][t] = d * inv_s;
    Z[sub][t] = (r == c) ? 1.f : 0.f;
    __syncthreads();

    for (int it = 0; it < 24; it++) {
        float acc = 0.f;
#pragma unroll
        for (int k = 0; k < 8; k++) acc += Z[sub][r * 8 + k] * Y[sub][k * 8 + c];
        float g = ((r == c) ? 1.5f : 0.f) - 0.5f * acc;
        __syncthreads();
        G[sub][t] = g;
        __syncthreads();
        float ny = 0.f, nz = 0.f;
#pragma unroll
        for (int k = 0; k < 8; k++) {
            ny += Y[sub][r * 8 + k] * G[sub][k * 8 + c];
            nz += G[sub][r * 8 + k] * Z[sub][k * 8 + c];
        }
        __syncthreads();
        Y[sub][t] = ny;
        Z[sub][t] = nz;
        __syncthreads();
    }

    if (v < n) g_dis[v * 64 + t] = Z[sub][t] * rsqrtf(s);
}

// ---- k_norm: N_p = R_p @ Dis[head(p)] for every directed edge ----
__global__ void k_norm(const float* __restrict__ R, const int* __restrict__ E, int P) {
    __shared__ float Rs[4][64], Ds[4][64];
    int sub = threadIdx.x >> 6;
    int t   = threadIdx.x & 63;
    int p   = blockIdx.x * 4 + sub;
    bool valid = (p < P);
    if (valid) {
        int j = E[2 * p + 1];            // head
        if (t < 16)
            ((float4*)Rs[sub])[t] = ((const float4*)(R + (size_t)p * 64))[t];
        else if (t < 32)
            ((float4*)Ds[sub])[t - 16] = ((const float4*)(g_dis + (size_t)j * 64))[t - 16];
    }
    __syncthreads();
    if (!valid) return;
    int r = t >> 3, c = t & 7;
    float4 a0 = ((const float4*)(Rs[sub] + r * 8))[0];
    float4 a1 = ((const float4*)(Rs[sub] + r * 8))[1];
    const float* Dc = Ds[sub] + c;
    float s = a0.x * Dc[0]  + a0.y * Dc[8]  + a0.z * Dc[16] + a0.w * Dc[24]
            + a1.x * Dc[32] + a1.y * Dc[40] + a1.z * Dc[48] + a1.w * Dc[56];
    g_norm[(size_t)p * 64 + t] = s;
}

// ---- stage edge blocks: -sgn * N_rev^T @ N_p (ONE matmul per block) ----
__global__ void k_stage_e(const int* __restrict__ E, const float* __restrict__ L1,
                          int P, int n) {
    __shared__ float M1T[4][64], M2[4][64];
    int sub = threadIdx.x >> 6;
    int t   = threadIdx.x & 63;
    int p   = blockIdx.x * 4 + sub;
    bool valid = (p < P);
    int i = 0, j = 0;
    if (valid) {
        int2 e = ((const int2*)E)[p];
        i = e.x; j = e.y;
        int half = P >> 1;
        int rev = (p < half) ? (p + half) : (p - half);
        if (t < 16) {
            // transpose N_rev on load: M1T[col*8+row] = N_rev[row*8+col]
            float4 v = ((const float4*)(g_norm + (size_t)rev * 64))[t];
            int row = t >> 1, c0 = (t & 1) * 4;
            M1T[sub][(c0 + 0) * 8 + row] = v.x;
            M1T[sub][(c0 + 1) * 8 + row] = v.y;
            M1T[sub][(c0 + 2) * 8 + row] = v.z;
            M1T[sub][(c0 + 3) * 8 + row] = v.w;
        } else if (t < 32) {
            ((float4*)M2[sub])[t - 16] = ((const float4*)(g_norm + (size_t)p * 64))[t - 16];
        }
    }
    __syncthreads();
    if (!valid) return;
    float l = L1[(size_t)i * n + j];
    float sgn = (l > 0.f) ? 1.f : ((l < 0.f) ? -1.f : 0.f);
    int r = t >> 3, c = t & 7;
    // (N_rev^T N_p)[r][c] = sum_k N_rev[k][r] * N_p[k][c] = sum_k M1T[r*8+k] * M2[k*8+c]
    float4 a0 = ((const float4*)(M1T[sub] + r * 8))[0];
    float4 a1 = ((const float4*)(M1T[sub] + r * 8))[1];
    const float* Bc = M2[sub] + c;
    float s = a0.x * Bc[0]  + a0.y * Bc[8]  + a0.z * Bc[16] + a0.w * Bc[24]
            + a1.x * Bc[32] + a1.y * Bc[40] + a1.z * Bc[48] + a1.w * Bc[56];
    g_stage[(size_t)p * 64 + t] = -sgn * s;
}

// ---- stage diagonal blocks: Dis_v @ diag_v @ Dis_v (n blocks, 2 matmuls) ----
__global__ void k_stage_d(int P, int n) {
    __shared__ float Di[4][64], B[4][64], T[4][64];
    int sub = threadIdx.x >> 6;
    int t   = threadIdx.x & 63;
    int v   = blockIdx.x * 4 + sub;
    bool valid = (v < n);
    if (valid) {
        if (t < 16)
            ((float4*)Di[sub])[t] = ((const float4*)(g_dis + (size_t)v * 64))[t];
        else if (t < 32)
            ((float4*)B[sub])[t - 16] = ((const float4*)(g_diag + (size_t)v * 64))[t - 16];
    }
    __syncthreads();
    int r = t >> 3, c = t & 7;
    if (valid) {
        float4 a0 = ((const float4*)(Di[sub] + r * 8))[0];
        float4 a1 = ((const float4*)(Di[sub] + r * 8))[1];
        const float* Bc = B[sub] + c;
        float s = a0.x * Bc[0]  + a0.y * Bc[8]  + a0.z * Bc[16] + a0.w * Bc[24]
                + a1.x * Bc[32] + a1.y * Bc[40] + a1.z * Bc[48] + a1.w * Bc[56];
        T[sub][t] = s;
    }
    __syncthreads();
    if (valid) {
        float4 a0 = ((const float4*)(T[sub] + r * 8))[0];
        float4 a1 = ((const float4*)(T[sub] + r * 8))[1];
        const float* Bc = Di[sub] + c;
        float s = a0.x * Bc[0]  + a0.y * Bc[8]  + a0.z * Bc[16] + a0.w * Bc[24]
                + a1.x * Bc[32] + a1.y * Bc[40] + a1.z * Bc[48] + a1.w * Bc[56];
        g_stage[(size_t)(P + v) * 64 + t] = s;
    }
}

// ---- scatter: copy staged blocks into the zeroed output (tiny tail) ----
__global__ void k_scatter(const int* __restrict__ E, float* __restrict__ out,
                          int P, int n) {
    int bid = blockIdx.x * 16 + (threadIdx.x >> 4);
    if (bid >= P + n) return;
    int l = threadIdx.x & 15;     // 0..15: (row, half)
    int r = l >> 1, h = l & 1;
    int i, j;
    if (bid < P) { int2 e = ((const int2*)E)[bid]; i = e.x; j = e.y; }
    else         { i = j = bid - P; }
    float4 v = ((const float4*)(g_stage + (size_t)bid * 64))[l];
    size_t nd = (size_t)n * 8;
    ((float4*)(out + ((size_t)i * 8 + r) * nd + (size_t)j * 8))[h] = v;
}

extern "C" void kernel_launch(void* const* d_in, const int* in_sizes, int n_in,
                              void* d_out, int out_size) {
    const float* R  = (const float*)d_in[0];  // (P, 8, 8)
    const int*   E  = (const int*)  d_in[1];  // (P, 2)
    const float* L1 = (const float*)d_in[3];  // (n, n)

    int P = in_sizes[1] / 2;
    int n = (int)(sqrt((double)in_sizes[3]) + 0.5);

    // one-time host-side resources (streams/events are NOT device memory)
    static bool inited = false;
    static cudaStream_t side;
    static cudaEvent_t ev_fork, ev_chain;
    static void* diag_ptr;
    if (!inited) {
        cudaStreamCreateWithFlags(&side, cudaStreamNonBlocking);
        cudaEventCreateWithFlags(&ev_fork, cudaEventDisableTiming);
        cudaEventCreateWithFlags(&ev_chain, cudaEventDisableTiming);
        cudaGetSymbolAddress(&diag_ptr, g_diag);
        inited = true;
    }

    // side stream (forked at t=0): chain + stage — no touches of d_out
    cudaEventRecord(ev_fork, 0);
    cudaStreamWaitEvent(side, ev_fork, 0);
    cudaMemsetAsync(diag_ptr, 0, (size_t)n * 64 * sizeof(float), side);
    k_ftf    <<<(P + 3) / 4, 256, 0, side>>>(R, E, P);
    k_ns     <<<(n + 3) / 4, 256, 0, side>>>(n);
    k_norm   <<<(P + 3) / 4, 256, 0, side>>>(R, E, P);
    k_stage_e<<<(P + 3) / 4, 256, 0, side>>>(E, L1, P, n);
    k_stage_d<<<(n + 3) / 4, 256, 0, side>>>(P, n);
    cudaEventRecord(ev_chain, side);

    // main stream: full TMA bulk-store zero (owns the machine)
    size_t total = (size_t)out_size * sizeof(float);
    size_t per_cta = (size_t)ZPER * ZCHUNK;
    int zgrid = (int)((total + per_cta - 1) / per_cta);
    k_zero_tma<<<zgrid, 128>>>((char*)d_out, total);

    // tiny tail: scatter staged blocks after zero + chain
    cudaStreamWaitEvent(0, ev_chain, 0);
    k_scatter<<<(P + n + 15) / 16, 256>>>(E, (float*)d_out, P, n);
}